// round 16
// baseline (speedup 1.0000x reference)
#include <cuda_runtime.h>
#include <cstdint>

// EMA along last axis: acc_t = w*x_t + (1-w)*acc_{t-1}
// [B,C,F,T] fp32, T=6000 contiguous; 4112 independent sequences.
//
// One WARP per sequence, 128-element segments (lane k owns times 4k..4k+3:
// every LDG.128/STG.128 is a dense 512B transaction). Carry chains in a
// register. Zero smem/barriers. 4-segment-deep load prefetch.
//
// R16 vs R12 (wall-best): the two segments already in hand per loop
// iteration are scanned with INTERLEAVED shuffle chains (2-way ILP:
// each of the 5 scan steps issues two independent SHFLs), halving the
// serial scan latency per iteration. Memory instruction stream is
// byte-identical to R12. L2 policy as R12: loads evict_last (input
// pinned), stores evict_first (writes stream).

constexpr int T_LEN     = 6000;
constexpr int SEG       = 128;                // 32 lanes x 4 floats
constexpr int NFULL     = T_LEN / SEG;        // 46
constexpr int REM       = T_LEN - NFULL*SEG;  // 112
constexpr int REM_LANES = REM / 4;            // 28
constexpr int WPB       = 4;                  // warps per block

__device__ __forceinline__ float4 ldg_hint(const float4* p, uint64_t pol) {
    float4 v;
    asm("ld.global.L2::cache_hint.v4.f32 {%0,%1,%2,%3}, [%4], %5;"
        : "=f"(v.x), "=f"(v.y), "=f"(v.z), "=f"(v.w) : "l"(p), "l"(pol));
    return v;
}
__device__ __forceinline__ void stg_hint(float4* p, float4 v, uint64_t pol) {
    asm volatile("st.global.L2::cache_hint.v4.f32 [%0], {%1,%2,%3,%4}, %5;"
                 :: "l"(p), "f"(v.x), "f"(v.y), "f"(v.z), "f"(v.w), "l"(pol)
                 : "memory");
}

__global__ __launch_bounds__(WPB * 32)
void ema_kernel(const float* __restrict__ x,
                const float* __restrict__ init,
                const float* __restrict__ wptr,
                float* __restrict__ out,
                int nseq)
{
    const int lane = threadIdx.x & 31;
    const int wid  = threadIdx.x >> 5;
    const int seq  = blockIdx.x * WPB + wid;
    if (seq >= nseq) return;                  // warp-uniform exit

    uint64_t pol_in, pol_out;
    asm("createpolicy.fractional.L2::evict_last.b64 %0, 1.0;"  : "=l"(pol_in));
    asm("createpolicy.fractional.L2::evict_first.b64 %0, 1.0;" : "=l"(pol_out));

    const float w  = fminf(fmaxf(wptr[0], 0.0f), 1.0f);
    const float a  = 1.0f - w;
    const float a2 = a * a;
    const float a3 = a2 * a;
    const float a4 = a2 * a2;
    const float alane = powf(a4, (float)lane);  // a^(4*lane)
    const float a128  = powf(a4, 32.0f);        // a^128

    const float4* xp = reinterpret_cast<const float4*>(x + (size_t)seq * T_LEN);
    float4*       op = reinterpret_cast<float4*>(out + (size_t)seq * T_LEN);

    float carry = init[seq];                  // state entering current segment

    // predicated dense segment load (seg j; j==NFULL is the 112-elem tail)
    auto load_seg = [&](int j) -> float4 {
        if (j < NFULL)                      return ldg_hint(xp + j * 32 + lane, pol_in);
        if (j == NFULL && lane < REM_LANES) return ldg_hint(xp + j * 32 + lane, pol_in);
        return make_float4(0.f, 0.f, 0.f, 0.f);
    };

    // two consecutive segments, shuffle chains interleaved (2-way ILP)
    auto process2 = [&](float4 c0, float4 c1, int segi, bool tail_pair) {
        // independent local chains (zero init)
        float l00 = w * c0.x;
        float l01 = fmaf(w, c0.y, a * l00);
        float l02 = fmaf(w, c0.z, a * l01);
        float l03 = fmaf(w, c0.w, a * l02);
        float l10 = w * c1.x;
        float l11 = fmaf(w, c1.y, a * l10);
        float l12 = fmaf(w, c1.z, a * l11);
        float l13 = fmaf(w, c1.w, a * l12);

        // interleaved inclusive affine scans: D_l = e_l + a4 * D_{l-1}
        float D0 = l03, D1 = l13;
        float sc = a4;
        #pragma unroll
        for (int s = 1; s < 32; s <<= 1) {
            float p0 = __shfl_up_sync(0xffffffffu, D0, s);
            float p1 = __shfl_up_sync(0xffffffffu, D1, s);
            if (lane >= s) {
                D0 = fmaf(sc, p0, D0);
                D1 = fmaf(sc, p1, D1);
            }
            sc *= sc;
        }
        float Dex0 = __shfl_up_sync(0xffffffffu, D0, 1);
        float Dex1 = __shfl_up_sync(0xffffffffu, D1, 1);
        if (lane == 0) { Dex0 = 0.0f; Dex1 = 0.0f; }
        float D31_0 = __shfl_sync(0xffffffffu, D0, 31);
        float D31_1 = __shfl_sync(0xffffffffu, D1, 31);

        // serial carry coupling across the pair
        float C0 = fmaf(alane, carry, Dex0);
        float carry_mid = fmaf(a128, carry, D31_0);
        float C1 = fmaf(alane, carry_mid, Dex1);
        carry = fmaf(a128, carry_mid, D31_1);

        float4 y0 = make_float4(fmaf(a,  C0, l00), fmaf(a2, C0, l01),
                                fmaf(a3, C0, l02), fmaf(a4, C0, l03));
        stg_hint(op + segi * 32 + lane, y0, pol_out);

        bool ok1 = !tail_pair || (lane < REM_LANES);
        if (ok1) {
            float4 y1 = make_float4(fmaf(a,  C1, l10), fmaf(a2, C1, l11),
                                    fmaf(a3, C1, l12), fmaf(a4, C1, l13));
            stg_hint(op + (segi + 1) * 32 + lane, y1, pol_out);
        }
    };

    // 4-deep prefetch: b0..b3 hold segments i..i+3
    float4 b0 = load_seg(0);
    float4 b1 = load_seg(1);
    float4 b2 = load_seg(2);
    float4 b3 = load_seg(3);

    #pragma unroll 1
    for (int i = 0; i < NFULL - 2; i += 2) {   // pairs (0,1)..(42,43)
        float4 c0 = b0, c1 = b1;
        b0 = b2; b1 = b3;
        // issue next loads BEFORE the scan chains
        b2 = load_seg(i + 4);
        b3 = load_seg(i + 5);
        process2(c0, c1, i, false);
    }
    // pair (44,45), then pair (46, tail-only) — b2 holds seg 46, b3 is zeros
    process2(b0, b1, NFULL - 2, false);
    // final: seg 46 (112 elems) processed as first of a pair whose second
    // element is all-zero and never stored
    {
        // process seg 46 alone via the pair path: store first, suppress second
        float4 c0 = b2;
        float l00 = w * c0.x;
        float l01 = fmaf(w, c0.y, a * l00);
        float l02 = fmaf(w, c0.z, a * l01);
        float l03 = fmaf(w, c0.w, a * l02);
        float D0 = l03, sc = a4;
        #pragma unroll
        for (int s = 1; s < 32; s <<= 1) {
            float p0 = __shfl_up_sync(0xffffffffu, D0, s);
            if (lane >= s) D0 = fmaf(sc, p0, D0);
            sc *= sc;
        }
        float Dex0 = __shfl_up_sync(0xffffffffu, D0, 1);
        if (lane == 0) Dex0 = 0.0f;
        float C0 = fmaf(alane, carry, Dex0);
        if (lane < REM_LANES) {
            float4 y0 = make_float4(fmaf(a,  C0, l00), fmaf(a2, C0, l01),
                                    fmaf(a3, C0, l02), fmaf(a4, C0, l03));
            stg_hint(op + NFULL * 32 + lane, y0, pol_out);
        }
    }
}

extern "C" void kernel_launch(void* const* d_in, const int* in_sizes, int n_in,
                              void* d_out, int out_size)
{
    const float* x    = (const float*)d_in[0];   // mag_spec  [B,C,F,T]
    const float* init = (const float*)d_in[1];   // initial_state [B,C,F,1]
    const float* wp   = (const float*)d_in[2];   // weights [1]
    float*       out  = (float*)d_out;

    const int nseq = in_sizes[1];                // B*C*F = 4112
    const int blocks = (nseq + WPB - 1) / WPB;   // 1028
    ema_kernel<<<blocks, WPB * 32>>>(x, init, wp, out, nseq);
}